// round 9
// baseline (speedup 1.0000x reference)
#include <cuda_runtime.h>
#include <cuda_fp16.h>
#include <cstddef>

// Digits_Caps dynamic routing. B=32, C=8192, U=32, K=16, I=16, 3 iters.
// pass1: W staged via cp.async to SMEM (coalesced, SW128-swizzled, double-buffered),
//        fp32 GEMM u_hat (2t x 16b/thread), register s~, fp16 u_hat store coalesced
// pass23: stream fp16 u_hat, routing update, weighted s~
// reduce/squash: partial reduction + normalize/squash

#define NSTRIPE 152
#define ELEMS 16384   // B*U*K
typedef unsigned long long ull;

// fp16 u_hat: [c][qq=0..3][t=0..511][8 halfs b=8qq..8qq+7] = 256 MB
static __device__ uint4 g_uhat[(size_t)8192 * 4 * 512];
static __device__ float g_spart[NSTRIPE * ELEMS];
static __device__ float g_zpart[NSTRIPE * 32];
static __device__ float g_sred[ELEMS];
static __device__ float g_zred[32];
static __device__ float g_v[ELEMS];
static __device__ float g_bij[8192 * 32];

__device__ __forceinline__ void ffma2(ull& d, const ull a, const ull b) {
  asm("fma.rn.f32x2 %0, %1, %2, %0;" : "+l"(d) : "l"(a), "l"(b));
}
__device__ __forceinline__ void add2(ull& d, const ull a) {
  asm("add.rn.f32x2 %0, %0, %1;" : "+l"(d) : "l"(a));
}
__device__ __forceinline__ ull dup2(float a) {
  unsigned u = __float_as_uint(a);
  return ((ull)u << 32) | u;
}
__device__ __forceinline__ float lo2(ull a) { return __uint_as_float((unsigned)a); }
__device__ __forceinline__ float hi2(ull a) { return __uint_as_float((unsigned)(a >> 32)); }
__device__ __forceinline__ unsigned f2h2(ull a) {   // {lo->low, hi->high}
  unsigned r;
  asm("cvt.rn.f16x2.f32 %0, %1, %2;" : "=r"(r)
      : "r"((unsigned)(a >> 32)), "r"((unsigned)a));
  return r;
}
__device__ __forceinline__ float2 h2f2(unsigned v) {
  __half2 h = *reinterpret_cast<__half2*>(&v);
  return __half22float2(h);
}
__device__ __forceinline__ void pref_l2(const void* p) {
  asm volatile("prefetch.global.L2 [%0];" :: "l"(p));
}
__device__ __forceinline__ unsigned smem_u32(const void* p) {
  unsigned a;
  asm("{ .reg .u64 t; cvta.to.shared.u64 t, %1; cvt.u32.u64 %0, t; }"
      : "=r"(a) : "l"(p));
  return a;
}
__device__ __forceinline__ void cpasync16(unsigned dst, const void* src) {
  asm volatile("cp.async.cg.shared.global [%0], [%1], 16;" :: "r"(dst), "l"(src));
}
__device__ __forceinline__ void cpasync_commit() {
  asm volatile("cp.async.commit_group;");
}
template <int N>
__device__ __forceinline__ void cpasync_wait() {
  asm volatile("cp.async.wait_group %0;" :: "n"(N));
}
__device__ __forceinline__ float4 lds128(unsigned addr) {
  float4 v;
  asm("ld.shared.v4.f32 {%0,%1,%2,%3}, [%4];"
      : "=f"(v.x), "=f"(v.y), "=f"(v.z), "=f"(v.w) : "r"(addr));
  return v;
}
// SW128 swizzle (Swizzle<3,4,3>): conflict-free for stride-64B per-thread reads
__device__ __forceinline__ unsigned swz(unsigned off) {
  return off ^ ((off >> 3) & 0x70);
}

// x_s layout: [j][i][b], i-stride 36 floats (16B aligned), j-stride 584
#define XS_J 584
#define XS_I 36
#define XS_BYTES (8 * XS_J * 4)   // 18688
// W double buffers, 1024-aligned
#define WOFF0 19456
#define WOFF1 (19456 + 32768)
#define SM_P1 (WOFF1 + 32768)     // 84992 B

// ---------------- pass 1: GEMM + fp16 u_hat store + register s~ -----------
__global__ __launch_bounds__(512, 1) void pass1_kernel(
    const float* __restrict__ x, const float* __restrict__ W) {
  extern __shared__ char smem_raw[];
  float* x_s = (float*)smem_raw;
  const unsigned wbase0 = smem_u32(smem_raw + WOFF0);
  const unsigned wbase1 = smem_u32(smem_raw + WOFF1);

  const int t = threadIdx.x;
  const int tl = t & 255;          // base t (also covers tl+256)
  const int bh = t >> 8;           // batch half
  const int bid = blockIdx.x;

  ull acc2[16];                    // register-resident s~ partials
#pragma unroll
  for (int p = 0; p < 16; p++) acc2[p] = 0ull;

  // preload first channel's W into buffer 0 (coalesced cp.async)
  {
    const int c0 = bid * 8;
    const float4* src = (const float4*)(W + (size_t)c0 * 8192);
#pragma unroll
    for (int r = 0; r < 4; r++) {
      const int e = t + r * 512;
      cpasync16(wbase0 + swz(e * 16), src + e);
    }
    cpasync_commit();
  }
  int par = 0;

  for (int chunk = bid; chunk < 1024; chunk += NSTRIPE) {
    __syncthreads();   // prior chunk fully consumed (x_s and W bufs)
    const int cbase = chunk * 8;
#pragma unroll
    for (int r = 0; r < 8; r++) {
      const int e = t + r * 512;
      const int j = e & 7, bi = e >> 3;
      const int i = bi & 15, b = bi >> 4;
      x_s[j * XS_J + i * XS_I + b] = x[(size_t)bi * 8192 + cbase + j];
    }

#pragma unroll 1
    for (int j = 0; j < 8; j++) {
      const int c = cbase + j;
      const unsigned wcur = par ? wbase1 : wbase0;
      const unsigned wnxt = par ? wbase0 : wbase1;

      __syncthreads();   // all threads done with wnxt's previous contents
                         // (and, on j==0, x_s staging complete)
      // issue next channel's W into the other buffer
      const int cn = (j < 7) ? (c + 1) : (chunk + NSTRIPE) * 8;
      if (cn < 8192) {
        const float4* src = (const float4*)(W + (size_t)cn * 8192);
#pragma unroll
        for (int r = 0; r < 4; r++) {
          const int e = t + r * 512;
          cpasync16(wnxt + swz(e * 16), src + e);
        }
        cpasync_commit();
        cpasync_wait<1>();   // current buffer's group has landed (this thread)
      } else {
        cpasync_wait<0>();
      }
      __syncthreads();       // current buffer landed for ALL threads

      ull uh2[16];   // [tp*8 + bp]
#pragma unroll
      for (int p = 0; p < 16; p++) uh2[p] = 0ull;

#pragma unroll
      for (int g = 0; g < 4; g++) {
        const unsigned offA = tl * 64 + g * 16;
        const unsigned offB = offA + 16384;   // (tl+256)*64
        const float4 va = lds128(wcur + swz(offA));
        const float4 vb = lds128(wcur + swz(offB));
        const float vaf[4] = {va.x, va.y, va.z, va.w};
        const float vbf[4] = {vb.x, vb.y, vb.z, vb.w};
#pragma unroll
        for (int ii = 0; ii < 4; ii++) {
          const int i = g * 4 + ii;
          const ull wA = dup2(vaf[ii]);
          const ull wB = dup2(vbf[ii]);
          const ulonglong2* xp =
              (const ulonglong2*)(x_s + j * XS_J + i * XS_I + bh * 16);
#pragma unroll
          for (int q = 0; q < 4; q++) {
            const ulonglong2 xv = xp[q];   // broadcast LDS.128 feeds 4 FFMA2
            ffma2(uh2[2*q],       wA, xv.x);
            ffma2(uh2[2*q + 1],   wA, xv.y);
            ffma2(uh2[8 + 2*q],   wB, xv.x);
            ffma2(uh2[8 + 2*q+1], wB, xv.y);
          }
        }
      }

      // fp16 store, fully coalesced: [c][qq][t]{8 halfs}, qq = 2*bh + qh
#pragma unroll
      for (int tp = 0; tp < 2; tp++) {
#pragma unroll
        for (int qh = 0; qh < 2; qh++) {
          uint4 o;
          o.x = f2h2(uh2[tp*8 + qh*4 + 0]);
          o.y = f2h2(uh2[tp*8 + qh*4 + 1]);
          o.z = f2h2(uh2[tp*8 + qh*4 + 2]);
          o.w = f2h2(uh2[tp*8 + qh*4 + 3]);
          g_uhat[(size_t)c * 2048 + (2*bh + qh) * 512 + tl + tp * 256] = o;
        }
      }
      // s~ accumulate in registers
#pragma unroll
      for (int p = 0; p < 16; p++) add2(acc2[p], uh2[p]);

      par ^= 1;
    }
  }

#pragma unroll
  for (int p = 0; p < 16; p++) {
    const ull v = acc2[p];
    const int b0 = bh * 16 + 2 * (p & 7);
    const int tg = tl + (p >> 3) * 256;
    g_spart[(size_t)bid * ELEMS + b0 * 512 + tg]       = lo2(v);
    g_spart[(size_t)bid * ELEMS + (b0 + 1) * 512 + tg] = hi2(v);
  }
}

// ---------------- passes 2/3: stream fp16 u_hat, routing update -----------
template <int MODE>
__global__ __launch_bounds__(256, 2) void pass23_kernel() {
  extern __shared__ float v_s[];   // [tid][b] stride 33
  const int tid = threadIdx.x;
  const int half = blockIdx.x & 1;
  const int stripe = blockIdx.x >> 1;
  const int tg = half * 256 + tid;
  const int u = tg >> 4;
  const int k = tg & 15;

#pragma unroll
  for (int b = 0; b < 32; b++) v_s[tid * 33 + b] = g_v[b * 512 + tg];
  __syncthreads();

  float acc[32];
#pragma unroll
  for (int b = 0; b < 32; b++) acc[b] = 0.f;
  float accz = 0.f;

  uint4 cur[4];
  {
    const uint4* up = g_uhat + (size_t)stripe * 2048 + tg;
#pragma unroll
    for (int qq = 0; qq < 4; qq++) cur[qq] = up[qq * 512];
  }

#pragma unroll 1
  for (int c = stripe; c < 8192; c += NSTRIPE) {
    const int cn = c + NSTRIPE;
    uint4 nxt[4];
    if (cn < 8192) {
      const uint4* up = g_uhat + (size_t)cn * 2048 + tg;
#pragma unroll
      for (int qq = 0; qq < 4; qq++) nxt[qq] = up[qq * 512];
      if (cn + NSTRIPE < 8192) {
        const uint4* pp = g_uhat + (size_t)(cn + NSTRIPE) * 2048 + tg;
#pragma unroll
        for (int qq = 0; qq < 4; qq++) pref_l2(pp + qq * 512);
      }
    }

    float part = 0.f;
#pragma unroll
    for (int qq = 0; qq < 4; qq++) {
      const unsigned hw[4] = {cur[qq].x, cur[qq].y, cur[qq].z, cur[qq].w};
#pragma unroll
      for (int w = 0; w < 4; w++) {
        const float2 f = h2f2(hw[w]);
        const int b0 = qq * 8 + w * 2;
        part = fmaf(f.x, v_s[tid * 33 + b0],     part);
        part = fmaf(f.y, v_s[tid * 33 + b0 + 1], part);
      }
    }
    part += __shfl_down_sync(0xffffffffu, part, 8, 16);
    part += __shfl_down_sync(0xffffffffu, part, 4, 16);
    part += __shfl_down_sync(0xffffffffu, part, 2, 16);
    part += __shfl_down_sync(0xffffffffu, part, 1, 16);

    float wt = 0.f;
    if (k == 0) {
      const float a = part * (1.f / 32.f);
      const float bnew = (MODE == 1) ? a : (g_bij[c * 32 + u] + a);
      if (MODE == 1) g_bij[c * 32 + u] = bnew;
      wt = __expf(bnew);
      accz += wt;
    }
    wt = __shfl_sync(0xffffffffu, wt, 0, 16);

#pragma unroll
    for (int qq = 0; qq < 4; qq++) {
      const unsigned hw[4] = {cur[qq].x, cur[qq].y, cur[qq].z, cur[qq].w};
#pragma unroll
      for (int w = 0; w < 4; w++) {
        const float2 f = h2f2(hw[w]);
        const int b0 = qq * 8 + w * 2;
        acc[b0]     = fmaf(wt, f.x, acc[b0]);
        acc[b0 + 1] = fmaf(wt, f.y, acc[b0 + 1]);
      }
    }

#pragma unroll
    for (int qq = 0; qq < 4; qq++) cur[qq] = nxt[qq];
  }

#pragma unroll
  for (int b = 0; b < 32; b++)
    g_spart[(size_t)stripe * ELEMS + b * 512 + tg] = acc[b];
  if (k == 0) g_zpart[stripe * 32 + u] = accz;
}

// ---------------- parallel partial reduction (4 threads / element) --------
template <bool WITH_Z>
__global__ void reduce_kernel() {
  __shared__ float red[512];
  __shared__ float zs[256];
  const int tid = threadIdx.x;
  const int sub = tid >> 7;            // 0..3, 38 partials each
  const int el = tid & 127;
  const int elem = blockIdx.x * 128 + el;

  float s = 0.f;
  const int p0 = sub * 38;
#pragma unroll 4
  for (int i = 0; i < 38; i++)
    s += g_spart[(size_t)(p0 + i) * ELEMS + elem];
  red[tid] = s;
  __syncthreads();
  if (sub == 0)
    g_sred[elem] = red[el] + red[128 + el] + red[256 + el] + red[384 + el];

  if (WITH_Z && blockIdx.x == 0) {
    if (tid < 256) {
      const int u = tid & 31, g = tid >> 5;
      float z = 0.f;
#pragma unroll 4
      for (int i = 0; i < 19; i++) z += g_zpart[(g * 19 + i) * 32 + u];
      zs[tid] = z;
    }
    __syncthreads();
    if (tid < 32) {
      float z = 0.f;
#pragma unroll
      for (int g = 0; g < 8; g++) z += zs[g * 32 + tid];
      g_zred[tid] = z;
    }
  }
}

// ---------------- squash --------------------------------------------------
template <int ZMODE, bool FINAL>
__global__ void squash_kernel(float* __restrict__ out) {
  const int gw = blockIdx.x * (blockDim.x >> 5) + (threadIdx.x >> 5);
  const int lane = threadIdx.x & 31;   // = u
  if (gw >= 512) return;
  const int b = gw >> 4, k = gw & 15;
  const int idx = (b * 32 + lane) * 16 + k;

  float s = g_sred[idx];
  const float Z = (ZMODE == 1) ? 8192.f : g_zred[lane];
  s /= Z;

  float msq = s * s;
#pragma unroll
  for (int o = 16; o > 0; o >>= 1) msq += __shfl_xor_sync(0xffffffffu, msq, o);

  const float v = (msq / (1.f + msq)) * s * rsqrtf(msq);
  if (FINAL) out[idx] = v;
  else       g_v[idx] = v;
}

extern "C" void kernel_launch(void* const* d_in, const int* in_sizes, int n_in,
                              void* d_out, int out_size) {
  const float* x = (const float*)d_in[0];   // (32,16,8192)
  const float* W = (const float*)d_in[1];   // (8192,32,16,16)
  if (n_in >= 2 && in_sizes[0] > in_sizes[1]) {
    const float* tmp = x; x = W; W = tmp;
  }
  float* out = (float*)d_out;

  const int SM_V = 256 * 33 * 4;   // 33792 B
  cudaFuncSetAttribute(pass1_kernel, cudaFuncAttributeMaxDynamicSharedMemorySize, SM_P1);
  cudaFuncSetAttribute(pass23_kernel<1>, cudaFuncAttributeMaxDynamicSharedMemorySize, SM_V);
  cudaFuncSetAttribute(pass23_kernel<2>, cudaFuncAttributeMaxDynamicSharedMemorySize, SM_V);

  // iter 1
  pass1_kernel<<<NSTRIPE, 512, SM_P1>>>(x, W);
  reduce_kernel<false><<<128, 512>>>();
  squash_kernel<1, false><<<16, 1024>>>(nullptr);
  // iter 2
  pass23_kernel<1><<<2 * NSTRIPE, 256, SM_V>>>();
  reduce_kernel<true><<<128, 512>>>();
  squash_kernel<2, false><<<16, 1024>>>(nullptr);
  // iter 3
  pass23_kernel<2><<<2 * NSTRIPE, 256, SM_V>>>();
  reduce_kernel<true><<<128, 512>>>();
  squash_kernel<2, true><<<16, 1024>>>(out);
}

// round 10
// speedup vs baseline: 1.0673x; 1.0673x over previous
#include <cuda_runtime.h>
#include <cuda_fp16.h>
#include <cstddef>

// Digits_Caps dynamic routing. B=32, C=8192, U=32, K=16, I=16, 3 iters.
// pass1: W staged per-warp via coalesced cp.async (private double buffers, NO CTA
//        barriers in channel loop), fp32 GEMM u_hat, register s~, fp16 store
// pass23: stream fp16 u_hat, routing update, weighted s~  (R7 version)
// reduce/squash: partial reduction + normalize/squash     (R7 version)

#define NSTRIPE 152
#define ELEMS 16384   // B*U*K
typedef unsigned long long ull;

// fp16 u_hat: [c][qq=0..3][t=0..511][8 halfs b=8qq..8qq+7] = 256 MB
static __device__ uint4 g_uhat[(size_t)8192 * 4 * 512];
static __device__ float g_spart[NSTRIPE * ELEMS];
static __device__ float g_zpart[NSTRIPE * 32];
static __device__ float g_sred[ELEMS];
static __device__ float g_zred[32];
static __device__ float g_v[ELEMS];
static __device__ float g_bij[8192 * 32];

__device__ __forceinline__ void ffma2(ull& d, const ull a, const ull b) {
  asm("fma.rn.f32x2 %0, %1, %2, %0;" : "+l"(d) : "l"(a), "l"(b));
}
__device__ __forceinline__ void add2(ull& d, const ull a) {
  asm("add.rn.f32x2 %0, %0, %1;" : "+l"(d) : "l"(a));
}
__device__ __forceinline__ ull dup2(float a) {
  unsigned u = __float_as_uint(a);
  return ((ull)u << 32) | u;
}
__device__ __forceinline__ float lo2(ull a) { return __uint_as_float((unsigned)a); }
__device__ __forceinline__ float hi2(ull a) { return __uint_as_float((unsigned)(a >> 32)); }
__device__ __forceinline__ unsigned f2h2(ull a) {   // {lo->low, hi->high}
  unsigned r;
  asm("cvt.rn.f16x2.f32 %0, %1, %2;" : "=r"(r)
      : "r"((unsigned)(a >> 32)), "r"((unsigned)a));
  return r;
}
__device__ __forceinline__ float2 h2f2(unsigned v) {
  __half2 h = *reinterpret_cast<__half2*>(&v);
  return __half22float2(h);
}
__device__ __forceinline__ void pref_l2(const void* p) {
  asm volatile("prefetch.global.L2 [%0];" :: "l"(p));
}
__device__ __forceinline__ unsigned smem_u32(const void* p) {
  unsigned a;
  asm("{ .reg .u64 t; cvta.to.shared.u64 t, %1; cvt.u32.u64 %0, t; }"
      : "=r"(a) : "l"(p));
  return a;
}
__device__ __forceinline__ void cpasync16(unsigned dst, const void* src) {
  asm volatile("cp.async.cg.shared.global [%0], [%1], 16;" :: "r"(dst), "l"(src));
}
__device__ __forceinline__ void cpasync_commit() {
  asm volatile("cp.async.commit_group;");
}
template <int N>
__device__ __forceinline__ void cpasync_wait() {
  asm volatile("cp.async.wait_group %0;" :: "n"(N));
}
__device__ __forceinline__ float4 lds128(unsigned addr) {
  float4 v;
  asm("ld.shared.v4.f32 {%0,%1,%2,%3}, [%4];"
      : "=f"(v.x), "=f"(v.y), "=f"(v.z), "=f"(v.w) : "r"(addr));
  return v;
}
// Swizzle<3,4,3>: XOR bits[6:4] with bits[9:7]; conflict-free for the
// stride-64B per-lane reads below (verified: all 32 banks distinct per phase)
__device__ __forceinline__ unsigned swz(unsigned off) {
  return off ^ ((off >> 3) & 0x70);
}

// x_s layout: [j][i][b], i-stride 36 floats (16B aligned), j-stride 584
#define XS_J 584
#define XS_I 36
#define XS_BYTES (8 * XS_J * 4)   // 18688
// per-warp W buffers: 16 warps x (2 bufs x 4096 B), 1024-aligned
#define WOFF 19456
#define SM_P1 (WOFF + 16 * 8192)  // 150528 B

// ---------------- pass 1: GEMM + fp16 u_hat store + register s~ -----------
__global__ __launch_bounds__(512, 1) void pass1_kernel(
    const float* __restrict__ x, const float* __restrict__ W) {
  extern __shared__ char smem_raw[];
  float* x_s = (float*)smem_raw;

  const int t = threadIdx.x;
  const int tl = t & 255;          // base t (also covers tl+256)
  const int bh = t >> 8;           // batch half
  const int w = t >> 5;            // warp 0..15
  const int ln = t & 31;
  const int bid = blockIdx.x;

  const unsigned wbuf0 = smem_u32(smem_raw + WOFF + w * 8192);
  const unsigned wbuf1 = wbuf0 + 4096;

  ull acc2[16];                    // register-resident s~ partials
#pragma unroll
  for (int p = 0; p < 16; p++) acc2[p] = 0ull;

  // stage channel c's W slice for this warp into buffer `base`:
  // A half (tl-range): 2048 B contiguous at W + c*8192 + (w&7)*512 floats
  // B half (tl+256):   2048 B contiguous at +16384 bytes
  auto stage = [&](unsigned base, int c) {
    const char* src = (const char*)(W + (size_t)c * 8192 + (w & 7) * 512);
#pragma unroll
    for (int r = 0; r < 4; r++)
      cpasync16(base + swz((r * 32 + ln) * 16), src + (r * 32 + ln) * 16);
#pragma unroll
    for (int r = 0; r < 4; r++)
      cpasync16(base + 2048 + swz((r * 32 + ln) * 16),
                src + 16384 + (r * 32 + ln) * 16);
  };

  // preload first channel (c = bid*8) into buf0
  stage(wbuf0, bid * 8);
  cpasync_commit();
  int par = 0;

  for (int chunk = bid; chunk < 1024; chunk += NSTRIPE) {
    __syncthreads();   // previous chunk done reading x_s
    const int cbase = chunk * 8;
#pragma unroll
    for (int r = 0; r < 8; r++) {
      const int e = t + r * 512;
      const int j = e & 7, bi = e >> 3;
      const int i = bi & 15, b = bi >> 4;
      x_s[j * XS_J + i * XS_I + b] = x[(size_t)bi * 8192 + cbase + j];
    }
    __syncthreads();   // x_s visible to all warps

#pragma unroll 1
    for (int j = 0; j < 8; j++) {
      const int c = cbase + j;
      const unsigned wcur = par ? wbuf1 : wbuf0;
      const unsigned wnxt = par ? wbuf0 : wbuf1;

      // issue next channel into the other private buffer, then ensure the
      // current one has landed (warp-local; no CTA barrier)
      const int cn = (j < 7) ? (c + 1) : (chunk + NSTRIPE) * 8;
      if (cn < 8192) {
        stage(wnxt, cn);
        cpasync_commit();
        cpasync_wait<1>();
      } else {
        cpasync_wait<0>();
      }
      __syncwarp();

      ull uh2[16];   // [tp*8 + bp]
#pragma unroll
      for (int p = 0; p < 16; p++) uh2[p] = 0ull;

#pragma unroll
      for (int g = 0; g < 4; g++) {
        const float4 va = lds128(wcur + swz(ln * 64 + g * 16));
        const float4 vb = lds128(wcur + 2048 + swz(ln * 64 + g * 16));
        const float vaf[4] = {va.x, va.y, va.z, va.w};
        const float vbf[4] = {vb.x, vb.y, vb.z, vb.w};
#pragma unroll
        for (int ii = 0; ii < 4; ii++) {
          const int i = g * 4 + ii;
          const ull wA = dup2(vaf[ii]);
          const ull wB = dup2(vbf[ii]);
          const ulonglong2* xp =
              (const ulonglong2*)(x_s + j * XS_J + i * XS_I + bh * 16);
#pragma unroll
          for (int q = 0; q < 4; q++) {
            const ulonglong2 xv = xp[q];   // broadcast LDS.128 feeds 4 FFMA2
            ffma2(uh2[2*q],       wA, xv.x);
            ffma2(uh2[2*q + 1],   wA, xv.y);
            ffma2(uh2[8 + 2*q],   wB, xv.x);
            ffma2(uh2[8 + 2*q+1], wB, xv.y);
          }
        }
      }

      // fp16 store, fully coalesced: [c][qq][t]{8 halfs}, qq = 2*bh + qh
#pragma unroll
      for (int tp = 0; tp < 2; tp++) {
#pragma unroll
        for (int qh = 0; qh < 2; qh++) {
          uint4 o;
          o.x = f2h2(uh2[tp*8 + qh*4 + 0]);
          o.y = f2h2(uh2[tp*8 + qh*4 + 1]);
          o.z = f2h2(uh2[tp*8 + qh*4 + 2]);
          o.w = f2h2(uh2[tp*8 + qh*4 + 3]);
          g_uhat[(size_t)c * 2048 + (2*bh + qh) * 512 + tl + tp * 256] = o;
        }
      }
      // s~ accumulate in registers
#pragma unroll
      for (int p = 0; p < 16; p++) add2(acc2[p], uh2[p]);

      par ^= 1;
    }
  }

#pragma unroll
  for (int p = 0; p < 16; p++) {
    const ull v = acc2[p];
    const int b0 = bh * 16 + 2 * (p & 7);
    const int tg = tl + (p >> 3) * 256;
    g_spart[(size_t)bid * ELEMS + b0 * 512 + tg]       = lo2(v);
    g_spart[(size_t)bid * ELEMS + (b0 + 1) * 512 + tg] = hi2(v);
  }
}

// ---------------- passes 2/3: stream fp16 u_hat, routing update -----------
template <int MODE>
__global__ __launch_bounds__(256, 2) void pass23_kernel() {
  extern __shared__ float v_s[];   // [tid][b] stride 33
  const int tid = threadIdx.x;
  const int half = blockIdx.x & 1;
  const int stripe = blockIdx.x >> 1;
  const int tg = half * 256 + tid;
  const int u = tg >> 4;
  const int k = tg & 15;

#pragma unroll
  for (int b = 0; b < 32; b++) v_s[tid * 33 + b] = g_v[b * 512 + tg];
  __syncthreads();

  float acc[32];
#pragma unroll
  for (int b = 0; b < 32; b++) acc[b] = 0.f;
  float accz = 0.f;

  uint4 cur[4];
  {
    const uint4* up = g_uhat + (size_t)stripe * 2048 + tg;
#pragma unroll
    for (int qq = 0; qq < 4; qq++) cur[qq] = up[qq * 512];
  }

#pragma unroll 1
  for (int c = stripe; c < 8192; c += NSTRIPE) {
    const int cn = c + NSTRIPE;
    uint4 nxt[4];
    if (cn < 8192) {
      const uint4* up = g_uhat + (size_t)cn * 2048 + tg;
#pragma unroll
      for (int qq = 0; qq < 4; qq++) nxt[qq] = up[qq * 512];
      if (cn + NSTRIPE < 8192) {
        const uint4* pp = g_uhat + (size_t)(cn + NSTRIPE) * 2048 + tg;
#pragma unroll
        for (int qq = 0; qq < 4; qq++) pref_l2(pp + qq * 512);
      }
    }

    float part = 0.f;
#pragma unroll
    for (int qq = 0; qq < 4; qq++) {
      const unsigned hw[4] = {cur[qq].x, cur[qq].y, cur[qq].z, cur[qq].w};
#pragma unroll
      for (int w = 0; w < 4; w++) {
        const float2 f = h2f2(hw[w]);
        const int b0 = qq * 8 + w * 2;
        part = fmaf(f.x, v_s[tid * 33 + b0],     part);
        part = fmaf(f.y, v_s[tid * 33 + b0 + 1], part);
      }
    }
    part += __shfl_down_sync(0xffffffffu, part, 8, 16);
    part += __shfl_down_sync(0xffffffffu, part, 4, 16);
    part += __shfl_down_sync(0xffffffffu, part, 2, 16);
    part += __shfl_down_sync(0xffffffffu, part, 1, 16);

    float wt = 0.f;
    if (k == 0) {
      const float a = part * (1.f / 32.f);
      const float bnew = (MODE == 1) ? a : (g_bij[c * 32 + u] + a);
      if (MODE == 1) g_bij[c * 32 + u] = bnew;
      wt = __expf(bnew);
      accz += wt;
    }
    wt = __shfl_sync(0xffffffffu, wt, 0, 16);

#pragma unroll
    for (int qq = 0; qq < 4; qq++) {
      const unsigned hw[4] = {cur[qq].x, cur[qq].y, cur[qq].z, cur[qq].w};
#pragma unroll
      for (int w = 0; w < 4; w++) {
        const float2 f = h2f2(hw[w]);
        const int b0 = qq * 8 + w * 2;
        acc[b0]     = fmaf(wt, f.x, acc[b0]);
        acc[b0 + 1] = fmaf(wt, f.y, acc[b0 + 1]);
      }
    }

#pragma unroll
    for (int qq = 0; qq < 4; qq++) cur[qq] = nxt[qq];
  }

#pragma unroll
  for (int b = 0; b < 32; b++)
    g_spart[(size_t)stripe * ELEMS + b * 512 + tg] = acc[b];
  if (k == 0) g_zpart[stripe * 32 + u] = accz;
}

// ---------------- parallel partial reduction (4 threads / element) --------
template <bool WITH_Z>
__global__ void reduce_kernel() {
  __shared__ float red[512];
  __shared__ float zs[256];
  const int tid = threadIdx.x;
  const int sub = tid >> 7;            // 0..3, 38 partials each
  const int el = tid & 127;
  const int elem = blockIdx.x * 128 + el;

  float s = 0.f;
  const int p0 = sub * 38;
#pragma unroll 4
  for (int i = 0; i < 38; i++)
    s += g_spart[(size_t)(p0 + i) * ELEMS + elem];
  red[tid] = s;
  __syncthreads();
  if (sub == 0)
    g_sred[elem] = red[el] + red[128 + el] + red[256 + el] + red[384 + el];

  if (WITH_Z && blockIdx.x == 0) {
    if (tid < 256) {
      const int u = tid & 31, g = tid >> 5;
      float z = 0.f;
#pragma unroll 4
      for (int i = 0; i < 19; i++) z += g_zpart[(g * 19 + i) * 32 + u];
      zs[tid] = z;
    }
    __syncthreads();
    if (tid < 32) {
      float z = 0.f;
#pragma unroll
      for (int g = 0; g < 8; g++) z += zs[g * 32 + tid];
      g_zred[tid] = z;
    }
  }
}

// ---------------- squash --------------------------------------------------
template <int ZMODE, bool FINAL>
__global__ void squash_kernel(float* __restrict__ out) {
  const int gw = blockIdx.x * (blockDim.x >> 5) + (threadIdx.x >> 5);
  const int lane = threadIdx.x & 31;   // = u
  if (gw >= 512) return;
  const int b = gw >> 4, k = gw & 15;
  const int idx = (b * 32 + lane) * 16 + k;

  float s = g_sred[idx];
  const float Z = (ZMODE == 1) ? 8192.f : g_zred[lane];
  s /= Z;

  float msq = s * s;
#pragma unroll
  for (int o = 16; o > 0; o >>= 1) msq += __shfl_xor_sync(0xffffffffu, msq, o);

  const float v = (msq / (1.f + msq)) * s * rsqrtf(msq);
  if (FINAL) out[idx] = v;
  else       g_v[idx] = v;
}

extern "C" void kernel_launch(void* const* d_in, const int* in_sizes, int n_in,
                              void* d_out, int out_size) {
  const float* x = (const float*)d_in[0];   // (32,16,8192)
  const float* W = (const float*)d_in[1];   // (8192,32,16,16)
  if (n_in >= 2 && in_sizes[0] > in_sizes[1]) {
    const float* tmp = x; x = W; W = tmp;
  }
  float* out = (float*)d_out;

  const int SM_V = 256 * 33 * 4;   // 33792 B
  cudaFuncSetAttribute(pass1_kernel, cudaFuncAttributeMaxDynamicSharedMemorySize, SM_P1);
  cudaFuncSetAttribute(pass23_kernel<1>, cudaFuncAttributeMaxDynamicSharedMemorySize, SM_V);
  cudaFuncSetAttribute(pass23_kernel<2>, cudaFuncAttributeMaxDynamicSharedMemorySize, SM_V);

  // iter 1
  pass1_kernel<<<NSTRIPE, 512, SM_P1>>>(x, W);
  reduce_kernel<false><<<128, 512>>>();
  squash_kernel<1, false><<<16, 1024>>>(nullptr);
  // iter 2
  pass23_kernel<1><<<2 * NSTRIPE, 256, SM_V>>>();
  reduce_kernel<true><<<128, 512>>>();
  squash_kernel<2, false><<<16, 1024>>>(nullptr);
  // iter 3
  pass23_kernel<2><<<2 * NSTRIPE, 256, SM_V>>>();
  reduce_kernel<true><<<128, 512>>>();
  squash_kernel<2, true><<<16, 1024>>>(out);
}

// round 11
// speedup vs baseline: 1.6426x; 1.5390x over previous
#include <cuda_runtime.h>
#include <cuda_fp16.h>
#include <cstddef>

// Digits_Caps dynamic routing. B=32, C=8192, U=32, K=16, I=16, 3 iters.
// pass1: HMMA (mma.sync m16n8k16 f16->f32) per-channel GEMM; W converted to fp16
//        per-warp (coalesced), x staged fp16; u_hat fp16 coalesced; s~ in regs
// pass23: stream fp16 u_hat, routing update, weighted s~  (unchanged)
// reduce/squash: partial reduction + normalize/squash     (unchanged)

#define NSTRIPE 152
#define ELEMS 16384   // B*U*K
typedef unsigned long long ull;

// fp16 u_hat: [c][qq=0..3][t=0..511][8 halfs b=8qq..8qq+7] = 256 MB
static __device__ uint4 g_uhat[(size_t)8192 * 4 * 512];
static __device__ float g_spart[NSTRIPE * ELEMS];
static __device__ float g_zpart[NSTRIPE * 32];
static __device__ float g_sred[ELEMS];
static __device__ float g_zred[32];
static __device__ float g_v[ELEMS];
static __device__ float g_bij[8192 * 32];

__device__ __forceinline__ float2 h2f2(unsigned v) {
  __half2 h = *reinterpret_cast<__half2*>(&v);
  return __half22float2(h);
}
__device__ __forceinline__ unsigned packh2(float lo, float hi) {
  unsigned r;
  asm("cvt.rn.f16x2.f32 %0, %1, %2;" : "=r"(r) : "f"(hi), "f"(lo));
  return r;
}
__device__ __forceinline__ void pref_l2(const void* p) {
  asm volatile("prefetch.global.L2 [%0];" :: "l"(p));
}
__device__ __forceinline__ unsigned smem_u32(const void* p) {
  unsigned a;
  asm("{ .reg .u64 t; cvta.to.shared.u64 t, %1; cvt.u32.u64 %0, t; }"
      : "=r"(a) : "l"(p));
  return a;
}
__device__ __forceinline__ void sts64(unsigned addr, unsigned p0, unsigned p1) {
  asm volatile("st.shared.v2.b32 [%0], {%1, %2};" :: "r"(addr), "r"(p0), "r"(p1));
}
__device__ __forceinline__ unsigned lds32(unsigned addr) {
  unsigned v;
  asm("ld.shared.b32 %0, [%1];" : "=r"(v) : "r"(addr));
  return v;
}
__device__ __forceinline__ void ldmatrix_x4(unsigned& r0, unsigned& r1,
                                            unsigned& r2, unsigned& r3,
                                            unsigned addr) {
  asm volatile("ldmatrix.sync.aligned.m8n8.x4.shared.b16 {%0,%1,%2,%3}, [%4];"
               : "=r"(r0), "=r"(r1), "=r"(r2), "=r"(r3) : "r"(addr));
}
__device__ __forceinline__ void mma16816(float& d0, float& d1, float& d2, float& d3,
                                         unsigned a0, unsigned a1, unsigned a2, unsigned a3,
                                         unsigned b0, unsigned b1) {
  asm volatile(
      "mma.sync.aligned.m16n8k16.row.col.f32.f16.f16.f32 "
      "{%0,%1,%2,%3}, {%4,%5,%6,%7}, {%8,%9}, {%10,%11,%12,%13};"
      : "=f"(d0), "=f"(d1), "=f"(d2), "=f"(d3)
      : "r"(a0), "r"(a1), "r"(a2), "r"(a3), "r"(b0), "r"(b1),
        "f"(0.f), "f"(0.f), "f"(0.f), "f"(0.f));
}

// smem map (pass1): x16 tiles then per-warp W fp16 double buffers.
// x16: [j=0..7][b=0..31 rows of 48 B][i*2]  (row stride 48 -> conflict-free frags)
// W16: per warp: 2 bufs x (32 t-rows x 48 B) ; row stride 48 -> conflict-free ldmatrix
#define XROW 48
#define XCH 1536              // 32 rows * 48
#define WAOFF 12288           // 8 * XCH
#define WBUF 1536             // 32 * 48
#define SM_P1 (WAOFF + 16 * 2 * WBUF)   // 12288 + 49152 = 61440

// ---------------- pass 1: HMMA GEMM + fp16 u_hat store + register s~ ------
__global__ __launch_bounds__(512, 1) void pass1_kernel(
    const float* __restrict__ x, const float* __restrict__ W) {
  extern __shared__ char sm[];
  const int t = threadIdx.x;
  const int w = t >> 5;            // warp 0..15, owns t-range [w*32, w*32+32)
  const int ln = t & 31;
  const int gid = ln >> 2;         // mma group id 0..7
  const int tig = ln & 3;          // thread in group
  const int bid = blockIdx.x;

  const unsigned xb = smem_u32(sm);
  const unsigned wa0 = xb + WAOFF + w * (2 * WBUF);
  const unsigned wa1 = wa0 + WBUF;

  // ldmatrix per-lane row address components (A tile 16x16, row stride 48 B)
  const unsigned lrow = (ln & 7) + ((ln >> 3) & 1) * 8;   // row within 16
  const unsigned lcol = (ln >> 4) * 16;                   // 0 or 16 B (k half)

  float sacc[32];                  // s~ partials: [m*16 + T*4 + d]
#pragma unroll
  for (int p = 0; p < 32; p++) sacc[p] = 0.f;

  // ---- W fp16 staging (warp-private, coalesced): channel c -> buf --------
  auto wstage_ld = [&](int c, float4* nv) {
    const float4* src = (const float4*)(W + (size_t)c * 8192 + w * 512);
#pragma unroll
    for (int r = 0; r < 4; r++) nv[r] = src[ln + r * 32];
  };
  auto wstage_st = [&](unsigned buf, const float4* nv) {
#pragma unroll
    for (int r = 0; r < 4; r++) {
      const int f = ln + r * 32;           // float4 index in 32t x 16i slice
      const int tl_ = f >> 2, q = f & 3;   // t-row, i-quad
      const unsigned p0 = packh2(nv[r].x, nv[r].y);
      const unsigned p1 = packh2(nv[r].z, nv[r].w);
      sts64(buf + tl_ * 48 + q * 8, p0, p1);
    }
  };

  // preload first channel into buf0
  {
    float4 nv[4];
    wstage_ld(bid * 8, nv);
    wstage_st(wa0, nv);
  }
  int par = 0;

  for (int chunk = bid; chunk < 1024; chunk += NSTRIPE) {
    __syncthreads();   // previous chunk done with x16
    const int cbase = chunk * 8;
    // stage x chunk as fp16 [j][b][i]
#pragma unroll
    for (int r = 0; r < 8; r++) {
      const int e = t + r * 512;
      const int j = e & 7, bi = e >> 3;
      const int i = bi & 15, b = bi >> 4;
      const float v = x[(size_t)bi * 8192 + cbase + j];
      *(__half*)(sm + j * XCH + b * XROW + i * 2) = __float2half(v);
    }
    __syncthreads();   // x16 visible; also orders W preload for j==0

#pragma unroll 1
    for (int j = 0; j < 8; j++) {
      const int c = cbase + j;
      const unsigned wcur = par ? wa1 : wa0;
      const unsigned wnxt = par ? wa0 : wa1;

      // issue next channel's W loads early (latency hidden by MMA work)
      const int cn = (j < 7) ? (c + 1) : (chunk + NSTRIPE) * 8;
      float4 nv[4];
      if (cn < 8192) wstage_ld(cn, nv);

      // B fragments: 4 n-tiles x 2 regs (k 0-7 / 8-15), from x16[j]
      unsigned bf[8];
#pragma unroll
      for (int T = 0; T < 4; T++) {
        const unsigned ba = xb + j * XCH + (T * 8 + gid) * XROW + tig * 4;
        bf[2 * T]     = lds32(ba);
        bf[2 * T + 1] = lds32(ba + 16);
      }

      const size_t gu_base = ((size_t)c * 2048) * 4;   // u32 units
      unsigned* gu = (unsigned*)g_uhat;

#pragma unroll
      for (int m = 0; m < 2; m++) {
        unsigned a0, a1, a2, a3;
        ldmatrix_x4(a0, a1, a2, a3, wcur + (m * 16 + lrow) * 48 + lcol);
        const int t0 = w * 32 + m * 16 + gid;
#pragma unroll
        for (int T = 0; T < 4; T++) {
          float d0, d1, d2, d3;
          mma16816(d0, d1, d2, d3, a0, a1, a2, a3, bf[2 * T], bf[2 * T + 1]);
          sacc[m * 16 + T * 4 + 0] += d0;
          sacc[m * 16 + T * 4 + 1] += d1;
          sacc[m * 16 + T * 4 + 2] += d2;
          sacc[m * 16 + T * 4 + 3] += d3;
          // coalesced u_hat store: rows t0 (d0,d1) and t0+8 (d2,d3)
          gu[gu_base + ((size_t)T * 512 + t0) * 4 + tig]       = packh2(d0, d1);
          gu[gu_base + ((size_t)T * 512 + t0 + 8) * 4 + tig]   = packh2(d2, d3);
        }
      }

      // store next channel's W into the other private buffer
      if (cn < 8192) wstage_st(wnxt, nv);
      __syncwarp();
      par ^= 1;
    }
  }

  // s~ partials -> g_spart[bid][b*512 + t]
#pragma unroll
  for (int m = 0; m < 2; m++) {
#pragma unroll
    for (int T = 0; T < 4; T++) {
      const int t0 = w * 32 + m * 16 + gid;
      const int b0 = T * 8 + 2 * tig;
      float* gp = g_spart + (size_t)bid * ELEMS;
      gp[(size_t)b0 * 512 + t0]           = sacc[m * 16 + T * 4 + 0];
      gp[(size_t)(b0 + 1) * 512 + t0]     = sacc[m * 16 + T * 4 + 1];
      gp[(size_t)b0 * 512 + t0 + 8]       = sacc[m * 16 + T * 4 + 2];
      gp[(size_t)(b0 + 1) * 512 + t0 + 8] = sacc[m * 16 + T * 4 + 3];
    }
  }
}

// ---------------- passes 2/3: stream fp16 u_hat, routing update -----------
template <int MODE>
__global__ __launch_bounds__(256, 2) void pass23_kernel() {
  extern __shared__ float v_s[];   // [tid][b] stride 33
  const int tid = threadIdx.x;
  const int half = blockIdx.x & 1;
  const int stripe = blockIdx.x >> 1;
  const int tg = half * 256 + tid;
  const int u = tg >> 4;
  const int k = tg & 15;

#pragma unroll
  for (int b = 0; b < 32; b++) v_s[tid * 33 + b] = g_v[b * 512 + tg];
  __syncthreads();

  float acc[32];
#pragma unroll
  for (int b = 0; b < 32; b++) acc[b] = 0.f;
  float accz = 0.f;

  uint4 cur[4];
  {
    const uint4* up = g_uhat + (size_t)stripe * 2048 + tg;
#pragma unroll
    for (int qq = 0; qq < 4; qq++) cur[qq] = up[qq * 512];
  }

#pragma unroll 1
  for (int c = stripe; c < 8192; c += NSTRIPE) {
    const int cn = c + NSTRIPE;
    uint4 nxt[4];
    if (cn < 8192) {
      const uint4* up = g_uhat + (size_t)cn * 2048 + tg;
#pragma unroll
      for (int qq = 0; qq < 4; qq++) nxt[qq] = up[qq * 512];
      if (cn + NSTRIPE < 8192) {
        const uint4* pp = g_uhat + (size_t)(cn + NSTRIPE) * 2048 + tg;
#pragma unroll
        for (int qq = 0; qq < 4; qq++) pref_l2(pp + qq * 512);
      }
    }

    float part = 0.f;
#pragma unroll
    for (int qq = 0; qq < 4; qq++) {
      const unsigned hw[4] = {cur[qq].x, cur[qq].y, cur[qq].z, cur[qq].w};
#pragma unroll
      for (int ww = 0; ww < 4; ww++) {
        const float2 f = h2f2(hw[ww]);
        const int b0 = qq * 8 + ww * 2;
        part = fmaf(f.x, v_s[tid * 33 + b0],     part);
        part = fmaf(f.y, v_s[tid * 33 + b0 + 1], part);
      }
    }
    part += __shfl_down_sync(0xffffffffu, part, 8, 16);
    part += __shfl_down_sync(0xffffffffu, part, 4, 16);
    part += __shfl_down_sync(0xffffffffu, part, 2, 16);
    part += __shfl_down_sync(0xffffffffu, part, 1, 16);

    float wt = 0.f;
    if (k == 0) {
      const float a = part * (1.f / 32.f);
      const float bnew = (MODE == 1) ? a : (g_bij[c * 32 + u] + a);
      if (MODE == 1) g_bij[c * 32 + u] = bnew;
      wt = __expf(bnew);
      accz += wt;
    }
    wt = __shfl_sync(0xffffffffu, wt, 0, 16);

#pragma unroll
    for (int qq = 0; qq < 4; qq++) {
      const unsigned hw[4] = {cur[qq].x, cur[qq].y, cur[qq].z, cur[qq].w};
#pragma unroll
      for (int ww = 0; ww < 4; ww++) {
        const float2 f = h2f2(hw[ww]);
        const int b0 = qq * 8 + ww * 2;
        acc[b0]     = fmaf(wt, f.x, acc[b0]);
        acc[b0 + 1] = fmaf(wt, f.y, acc[b0 + 1]);
      }
    }

#pragma unroll
    for (int qq = 0; qq < 4; qq++) cur[qq] = nxt[qq];
  }

#pragma unroll
  for (int b = 0; b < 32; b++)
    g_spart[(size_t)stripe * ELEMS + b * 512 + tg] = acc[b];
  if (k == 0) g_zpart[stripe * 32 + u] = accz;
}

// ---------------- parallel partial reduction (4 threads / element) --------
template <bool WITH_Z>
__global__ void reduce_kernel() {
  __shared__ float red[512];
  __shared__ float zs[256];
  const int tid = threadIdx.x;
  const int sub = tid >> 7;            // 0..3, 38 partials each
  const int el = tid & 127;
  const int elem = blockIdx.x * 128 + el;

  float s = 0.f;
  const int p0 = sub * 38;
#pragma unroll 4
  for (int i = 0; i < 38; i++)
    s += g_spart[(size_t)(p0 + i) * ELEMS + elem];
  red[tid] = s;
  __syncthreads();
  if (sub == 0)
    g_sred[elem] = red[el] + red[128 + el] + red[256 + el] + red[384 + el];

  if (WITH_Z && blockIdx.x == 0) {
    if (tid < 256) {
      const int u = tid & 31, g = tid >> 5;
      float z = 0.f;
#pragma unroll 4
      for (int i = 0; i < 19; i++) z += g_zpart[(g * 19 + i) * 32 + u];
      zs[tid] = z;
    }
    __syncthreads();
    if (tid < 32) {
      float z = 0.f;
#pragma unroll
      for (int g = 0; g < 8; g++) z += zs[g * 32 + tid];
      g_zred[tid] = z;
    }
  }
}

// ---------------- squash --------------------------------------------------
template <int ZMODE, bool FINAL>
__global__ void squash_kernel(float* __restrict__ out) {
  const int gw = blockIdx.x * (blockDim.x >> 5) + (threadIdx.x >> 5);
  const int lane = threadIdx.x & 31;   // = u
  if (gw >= 512) return;
  const int b = gw >> 4, k = gw & 15;
  const int idx = (b * 32 + lane) * 16 + k;

  float s = g_sred[idx];
  const float Z = (ZMODE == 1) ? 8192.f : g_zred[lane];
  s /= Z;

  float msq = s * s;
#pragma unroll
  for (int o = 16; o > 0; o >>= 1) msq += __shfl_xor_sync(0xffffffffu, msq, o);

  const float v = (msq / (1.f + msq)) * s * rsqrtf(msq);
  if (FINAL) out[idx] = v;
  else       g_v[idx] = v;
}

extern "C" void kernel_launch(void* const* d_in, const int* in_sizes, int n_in,
                              void* d_out, int out_size) {
  const float* x = (const float*)d_in[0];   // (32,16,8192)
  const float* W = (const float*)d_in[1];   // (8192,32,16,16)
  if (n_in >= 2 && in_sizes[0] > in_sizes[1]) {
    const float* tmp = x; x = W; W = tmp;
  }
  float* out = (float*)d_out;

  const int SM_V = 256 * 33 * 4;   // 33792 B
  cudaFuncSetAttribute(pass1_kernel, cudaFuncAttributeMaxDynamicSharedMemorySize, SM_P1);
  cudaFuncSetAttribute(pass23_kernel<1>, cudaFuncAttributeMaxDynamicSharedMemorySize, SM_V);
  cudaFuncSetAttribute(pass23_kernel<2>, cudaFuncAttributeMaxDynamicSharedMemorySize, SM_V);

  // iter 1
  pass1_kernel<<<NSTRIPE, 512, SM_P1>>>(x, W);
  reduce_kernel<false><<<128, 512>>>();
  squash_kernel<1, false><<<16, 1024>>>(nullptr);
  // iter 2
  pass23_kernel<1><<<2 * NSTRIPE, 256, SM_V>>>();
  reduce_kernel<true><<<128, 512>>>();
  squash_kernel<2, false><<<16, 1024>>>(nullptr);
  // iter 3
  pass23_kernel<2><<<2 * NSTRIPE, 256, SM_V>>>();
  reduce_kernel<true><<<128, 512>>>();
  squash_kernel<2, true><<<16, 1024>>>(out);
}